// round 9
// baseline (speedup 1.0000x reference)
#include <cuda_runtime.h>

#define DD 160
#define HH 192
#define WW 160
#define DHW (DD*HH*WW)

// output tile per block
#define TX 32
#define TY 8
#define TZ 4
// staged window: [base-PLO, base+tile+PLO] (+1 for far corner)
#define PLO 5
#define WX (TX + 11)   // 43  (odd stride -> conflict-free-ish LDS)
#define WY (TY + 11)   // 19
#define WZ (TZ + 11)   // 15
#define SN (WZ * WY * WX)  // 12255 floats = 49020 B

__device__ __forceinline__ float sample1_global(const float* __restrict__ v,
                                                float ix, float iy, float iz) {
    if (ix <= -1.0f || ix >= (float)WW ||
        iy <= -1.0f || iy >= (float)HH ||
        iz <= -1.0f || iz >= (float)DD) return 0.0f;
    float x0f = floorf(ix), y0f = floorf(iy), z0f = floorf(iz);
    int x0 = (int)x0f, y0 = (int)y0f, z0 = (int)z0f;
    float tx = ix - x0f, ty = iy - y0f, tz = iz - z0f;
    float acc = 0.0f;
    #pragma unroll
    for (int dz = 0; dz < 2; dz++) {
        int zc = z0 + dz;
        if ((unsigned)zc >= (unsigned)DD) continue;
        float wz = dz ? tz : 1.0f - tz;
        #pragma unroll
        for (int dy = 0; dy < 2; dy++) {
            int yc = y0 + dy;
            if ((unsigned)yc >= (unsigned)HH) continue;
            float wy = dy ? ty : 1.0f - ty;
            float wzy = wz * wy;
            unsigned base = ((unsigned)zc * HH + (unsigned)yc) * WW;
            #pragma unroll
            for (int dx = 0; dx < 2; dx++) {
                int xc = x0 + dx;
                if ((unsigned)xc >= (unsigned)WW) continue;
                float w = wzy * (dx ? tx : 1.0f - tx);
                acc = fmaf(w, __ldg(v + base + (unsigned)xc), acc);
            }
        }
    }
    return acc;
}

__device__ __forceinline__ void sample3(const float* __restrict__ v,
                                        float ix, float iy, float iz,
                                        float& o0, float& o1, float& o2) {
    o0 = 0.0f; o1 = 0.0f; o2 = 0.0f;
    // practically always fully out of bounds -> warp-uniform early-out
    if (ix <= -1.0f || ix >= (float)WW ||
        iy <= -1.0f || iy >= (float)HH ||
        iz <= -1.0f || iz >= (float)DD) return;
    float x0f = floorf(ix), y0f = floorf(iy), z0f = floorf(iz);
    int x0 = (int)x0f, y0 = (int)y0f, z0 = (int)z0f;
    float tx = ix - x0f, ty = iy - y0f, tz = iz - z0f;
    #pragma unroll
    for (int dz = 0; dz < 2; dz++) {
        int zc = z0 + dz;
        if ((unsigned)zc >= (unsigned)DD) continue;
        float wz = dz ? tz : 1.0f - tz;
        #pragma unroll
        for (int dy = 0; dy < 2; dy++) {
            int yc = y0 + dy;
            if ((unsigned)yc >= (unsigned)HH) continue;
            float wy = dy ? ty : 1.0f - ty;
            float wzy = wz * wy;
            unsigned base = ((unsigned)zc * HH + (unsigned)yc) * WW;
            #pragma unroll
            for (int dx = 0; dx < 2; dx++) {
                int xc = x0 + dx;
                if ((unsigned)xc >= (unsigned)WW) continue;
                float w = wzy * (dx ? tx : 1.0f - tx);
                unsigned off = base + (unsigned)xc;
                o0 = fmaf(w, __ldg(v + off), o0);
                o1 = fmaf(w, __ldg(v + DHW + off), o1);
                o2 = fmaf(w, __ldg(v + 2u*DHW + off), o2);
            }
        }
    }
}

__global__ void __launch_bounds__(256) st_kernel(
                          const float* __restrict__ src,
                          const float* __restrict__ flow1,
                          const float* __restrict__ flow2,
                          const float* __restrict__ rf_p,
                          float* __restrict__ out) {
    __shared__ float tile[SN];

    const int xb = blockIdx.x * TX;
    const int yb = blockIdx.y * TY;
    const int zb = blockIdx.z * TZ;
    const int wxb = xb - PLO, wyb = yb - PLO, wzb = zb - PLO;

    // ---- cooperative fill, structured (no div/mod) ----
    // zi strided by threadIdx.y, yi sequential, xi strided by threadIdx.x
    for (int zi = threadIdx.y; zi < WZ; zi += TY) {
        int gz = wzb + zi;
        bool zok = (unsigned)gz < (unsigned)DD;
        const float* srow = src + (unsigned)(gz * (HH * WW));
        float* trowz = tile + zi * (WY * WX);
        for (int yi = 0; yi < WY; yi++) {
            int gy = wyb + yi;
            bool yok = zok & ((unsigned)gy < (unsigned)HH);
            const float* sr = srow + (unsigned)(gy * WW);
            float* tr = trowz + yi * WX;
            #pragma unroll
            for (int xi = threadIdx.x; xi < WX; xi += 32) {
                int gx = wxb + xi;
                float val = 0.0f;
                if (yok & ((unsigned)gx < (unsigned)WW))
                    val = __ldg(sr + gx);
                tr[xi] = val;
            }
        }
    }
    __syncthreads();

    const int x = xb + threadIdx.x;
    const int y = yb + threadIdx.y;
    const float xf = (float)x, yf = (float)y;
    const float rf = __ldg(rf_p);

    unsigned idx0 = ((unsigned)zb * HH + (unsigned)y) * WW + (unsigned)x;

    // front-batched flow2 loads across the 4 z (MLP = 12)
    float f2z[TZ], f2y[TZ], f2x[TZ];
    #pragma unroll
    for (int j = 0; j < TZ; j++) {
        unsigned idx = idx0 + j * (unsigned)(HH * WW);
        f2z[j] = __ldg(flow2 + idx);
        f2y[j] = __ldg(flow2 + DHW + idx);
        f2x[j] = __ldg(flow2 + 2u*DHW + idx);
    }

    #pragma unroll
    for (int j = 0; j < TZ; j++) {
        unsigned idx = idx0 + j * (unsigned)(HH * WW);
        float zf = (float)(zb + j);

        // grid2 = grid + flow2 * rf  (grid analytic)
        float g2z = zf + f2z[j] * rf;
        float g2y = yf + f2y[j] * rf;
        float g2x = xf + f2x[j] * rf;

        // grid_sample(flow1, grid2) unnorm (align_corners=False)
        float ix1 = ((g2x + 1.0f) * (float)WW - 1.0f) * 0.5f;
        float iy1 = ((g2y + 1.0f) * (float)HH - 1.0f) * 0.5f;
        float iz1 = ((g2z + 1.0f) * (float)DD - 1.0f) * 0.5f;

        float w0, w1, w2;
        sample3(flow1, ix1, iy1, iz1, w0, w1, w2);

        // out_flow = flow1_warped + flow2
        float oz = w0 + f2z[j];
        float oy = w1 + f2y[j];
        float ox = w2 + f2x[j];

        // new_locs_total -> normalize -> unnorm (same fp order as reference)
        float vz = zf + oz * rf;
        float vy = yf + oy * rf;
        float vx = xf + ox * rf;

        float nz = 2.0f * (vz / (float)(DD - 1) - 0.5f);
        float ny = 2.0f * (vy / (float)(HH - 1) - 0.5f);
        float nx = 2.0f * (vx / (float)(WW - 1) - 0.5f);

        float sx = ((nx + 1.0f) * (float)WW - 1.0f) * 0.5f;
        float sy = ((ny + 1.0f) * (float)HH - 1.0f) * 0.5f;
        float sz = ((nz + 1.0f) * (float)DD - 1.0f) * 0.5f;

        // ---- trilinear sample of src: smem fast path ----
        float x0f = floorf(sx), y0f = floorf(sy), z0f = floorf(sz);
        int x0 = (int)x0f, y0 = (int)y0f, z0 = (int)z0f;
        float txf = sx - x0f, tyf = sy - y0f, tzf = sz - z0f;

        int xi = x0 - wxb, yi = y0 - wyb, zi = z0 - wzb;
        bool inwin = ((unsigned)xi < (unsigned)(WX - 1)) &
                     ((unsigned)yi < (unsigned)(WY - 1)) &
                     ((unsigned)zi < (unsigned)(WZ - 1));

        float img;
        if (inwin) {
            // window cells outside the volume are zero-filled; zero their
            // weights too -> exact zeros padding
            float wx0 = ((unsigned)x0       < (unsigned)WW) ? (1.0f - txf) : 0.0f;
            float wx1 = ((unsigned)(x0 + 1) < (unsigned)WW) ? txf : 0.0f;
            float wy0 = ((unsigned)y0       < (unsigned)HH) ? (1.0f - tyf) : 0.0f;
            float wy1 = ((unsigned)(y0 + 1) < (unsigned)HH) ? tyf : 0.0f;
            float wz0 = ((unsigned)z0       < (unsigned)DD) ? (1.0f - tzf) : 0.0f;
            float wz1 = ((unsigned)(z0 + 1) < (unsigned)DD) ? tzf : 0.0f;

            int b00 = (zi * WY + yi) * WX + xi;
            int b01 = b00 + WX;
            int b10 = b00 + WY * WX;
            int b11 = b10 + WX;

            float r00 = fmaf(tile[b00], wx0, tile[b00 + 1] * wx1);
            float r01 = fmaf(tile[b01], wx0, tile[b01 + 1] * wx1);
            float r10 = fmaf(tile[b10], wx0, tile[b10 + 1] * wx1);
            float r11 = fmaf(tile[b11], wx0, tile[b11 + 1] * wx1);

            img = wz0 * fmaf(wy0, r00, wy1 * r01)
                + wz1 * fmaf(wy0, r10, wy1 * r11);
        } else {
            img = sample1_global(src, sx, sy, sz);
        }

        out[idx]          = img;
        out[DHW + idx]    = oz;
        out[2u*DHW + idx] = oy;
        out[3u*DHW + idx] = ox;
    }
}

extern "C" void kernel_launch(void* const* d_in, const int* in_sizes, int n_in,
                              void* d_out, int out_size) {
    const float* src   = (const float*)d_in[0];
    const float* flow1 = (const float*)d_in[1];
    const float* flow2 = (const float*)d_in[2];
    // d_in[3] meshgrid — analytic, not loaded
    const float* rf    = (const float*)d_in[4];
    float* out = (float*)d_out;

    dim3 block(32, 8);
    dim3 grid(WW / TX, HH / TY, DD / TZ);
    st_kernel<<<grid, block>>>(src, flow1, flow2, rf, out);
}

// round 10
// speedup vs baseline: 1.4166x; 1.4166x over previous
#include <cuda_runtime.h>

#define DD 160
#define HH 192
#define WW 160
#define DHW (DD*HH*WW)

// output tile per block
#define TX 32
#define TY 8
#define TZ 4
// staged window: [base-PLO, base+tile+PLO] (+1 for far corner)
#define PLO 5
#define WX (TX + 11)   // 43  (odd stride -> bank-friendly LDS)
#define WY (TY + 11)   // 19
#define WZ (TZ + 11)   // 15
#define NROWS (WY * WZ)      // 285
#define SN (WZ * WY * WX)    // 12255 floats = 49020 B

__device__ __forceinline__ float sample1_global(const float* __restrict__ v,
                                                float ix, float iy, float iz) {
    if (ix <= -1.0f || ix >= (float)WW ||
        iy <= -1.0f || iy >= (float)HH ||
        iz <= -1.0f || iz >= (float)DD) return 0.0f;
    float x0f = floorf(ix), y0f = floorf(iy), z0f = floorf(iz);
    int x0 = (int)x0f, y0 = (int)y0f, z0 = (int)z0f;
    float tx = ix - x0f, ty = iy - y0f, tz = iz - z0f;
    float acc = 0.0f;
    #pragma unroll
    for (int dz = 0; dz < 2; dz++) {
        int zc = z0 + dz;
        if ((unsigned)zc >= (unsigned)DD) continue;
        float wz = dz ? tz : 1.0f - tz;
        #pragma unroll
        for (int dy = 0; dy < 2; dy++) {
            int yc = y0 + dy;
            if ((unsigned)yc >= (unsigned)HH) continue;
            float wy = dy ? ty : 1.0f - ty;
            float wzy = wz * wy;
            unsigned base = ((unsigned)zc * HH + (unsigned)yc) * WW;
            #pragma unroll
            for (int dx = 0; dx < 2; dx++) {
                int xc = x0 + dx;
                if ((unsigned)xc >= (unsigned)WW) continue;
                float w = wzy * (dx ? tx : 1.0f - tx);
                acc = fmaf(w, __ldg(v + base + (unsigned)xc), acc);
            }
        }
    }
    return acc;
}

__device__ __forceinline__ void sample3(const float* __restrict__ v,
                                        float ix, float iy, float iz,
                                        float& o0, float& o1, float& o2) {
    o0 = 0.0f; o1 = 0.0f; o2 = 0.0f;
    // practically always fully out of bounds -> warp-uniform early-out
    if (ix <= -1.0f || ix >= (float)WW ||
        iy <= -1.0f || iy >= (float)HH ||
        iz <= -1.0f || iz >= (float)DD) return;
    float x0f = floorf(ix), y0f = floorf(iy), z0f = floorf(iz);
    int x0 = (int)x0f, y0 = (int)y0f, z0 = (int)z0f;
    float tx = ix - x0f, ty = iy - y0f, tz = iz - z0f;
    #pragma unroll
    for (int dz = 0; dz < 2; dz++) {
        int zc = z0 + dz;
        if ((unsigned)zc >= (unsigned)DD) continue;
        float wz = dz ? tz : 1.0f - tz;
        #pragma unroll
        for (int dy = 0; dy < 2; dy++) {
            int yc = y0 + dy;
            if ((unsigned)yc >= (unsigned)HH) continue;
            float wy = dy ? ty : 1.0f - ty;
            float wzy = wz * wy;
            unsigned base = ((unsigned)zc * HH + (unsigned)yc) * WW;
            #pragma unroll
            for (int dx = 0; dx < 2; dx++) {
                int xc = x0 + dx;
                if ((unsigned)xc >= (unsigned)WW) continue;
                float w = wzy * (dx ? tx : 1.0f - tx);
                unsigned off = base + (unsigned)xc;
                o0 = fmaf(w, __ldg(v + off), o0);
                o1 = fmaf(w, __ldg(v + DHW + off), o1);
                o2 = fmaf(w, __ldg(v + 2u*DHW + off), o2);
            }
        }
    }
}

__global__ void __launch_bounds__(256) st_kernel(
                          const float* __restrict__ src,
                          const float* __restrict__ flow1,
                          const float* __restrict__ flow2,
                          const float* __restrict__ rf_p,
                          float* __restrict__ out) {
    __shared__ float tile[SN];

    const int xb = blockIdx.x * TX;
    const int yb = blockIdx.y * TY;
    const int zb = blockIdx.z * TZ;
    const int wxb = xb - PLO, wyb = yb - PLO, wzb = zb - PLO;

    const int lane = threadIdx.x;
    const int wid  = threadIdx.y;

    const int x = xb + lane;
    const int y = yb + wid;
    const float rf = __ldg(rf_p);

    unsigned idx0 = ((unsigned)zb * HH + (unsigned)y) * WW + (unsigned)x;

    // flow2 preload first -> overlaps fill latency (MLP = 12)
    float f2z[TZ], f2y[TZ], f2x[TZ];
    #pragma unroll
    for (int j = 0; j < TZ; j++) {
        unsigned idx = idx0 + j * (unsigned)(HH * WW);
        f2z[j] = __ldg(flow2 + idx);
        f2y[j] = __ldg(flow2 + DHW + idx);
        f2x[j] = __ldg(flow2 + 2u*DHW + idx);
    }

    // ---- cooperative fill: warp per row, lanes over x ----
    // Out-of-volume cells are filled with border-clamped values: they are
    // only ever multiplied by weights that the bounds masks zero out.
    {
        // clamped x coords for this lane's two positions (row-invariant)
        int gx0 = min(max(wxb + lane, 0), WW - 1);
        int gx1 = min(max(wxb + lane + 32, 0), WW - 1);
        #pragma unroll 4
        for (int r = wid; r < NROWS; r += TY) {
            int zi = r / WY;              // div by constant 19 -> mulhi
            int yi = r - zi * WY;
            int gz = min(max(wzb + zi, 0), DD - 1);
            int gy = min(max(wyb + yi, 0), HH - 1);
            const float* sr = src + ((unsigned)gz * HH + (unsigned)gy) * WW;
            float* tr = tile + r * WX;
            tr[lane] = __ldg(sr + gx0);
            if (lane < WX - 32)
                tr[lane + 32] = __ldg(sr + gx1);
        }
    }
    __syncthreads();

    const float xf = (float)x, yf = (float)y;

    #pragma unroll
    for (int j = 0; j < TZ; j++) {
        unsigned idx = idx0 + j * (unsigned)(HH * WW);
        float zf = (float)(zb + j);

        // grid2 = grid + flow2 * rf  (grid analytic)
        float g2z = zf + f2z[j] * rf;
        float g2y = yf + f2y[j] * rf;
        float g2x = xf + f2x[j] * rf;

        // grid_sample(flow1, grid2) unnorm (align_corners=False)
        float ix1 = ((g2x + 1.0f) * (float)WW - 1.0f) * 0.5f;
        float iy1 = ((g2y + 1.0f) * (float)HH - 1.0f) * 0.5f;
        float iz1 = ((g2z + 1.0f) * (float)DD - 1.0f) * 0.5f;

        float w0, w1, w2;
        sample3(flow1, ix1, iy1, iz1, w0, w1, w2);

        // out_flow = flow1_warped + flow2
        float oz = w0 + f2z[j];
        float oy = w1 + f2y[j];
        float ox = w2 + f2x[j];

        // new_locs_total -> normalize -> unnorm (same fp order as reference)
        float vz = zf + oz * rf;
        float vy = yf + oy * rf;
        float vx = xf + ox * rf;

        float nz = 2.0f * (vz / (float)(DD - 1) - 0.5f);
        float ny = 2.0f * (vy / (float)(HH - 1) - 0.5f);
        float nx = 2.0f * (vx / (float)(WW - 1) - 0.5f);

        float sx = ((nx + 1.0f) * (float)WW - 1.0f) * 0.5f;
        float sy = ((ny + 1.0f) * (float)HH - 1.0f) * 0.5f;
        float sz = ((nz + 1.0f) * (float)DD - 1.0f) * 0.5f;

        // ---- trilinear sample of src: smem fast path ----
        float x0f = floorf(sx), y0f = floorf(sy), z0f = floorf(sz);
        int x0 = (int)x0f, y0 = (int)y0f, z0 = (int)z0f;
        float txf = sx - x0f, tyf = sy - y0f, tzf = sz - z0f;

        int xi = x0 - wxb, yi = y0 - wyb, zi = z0 - wzb;
        bool inwin = ((unsigned)xi < (unsigned)(WX - 1)) &
                     ((unsigned)yi < (unsigned)(WY - 1)) &
                     ((unsigned)zi < (unsigned)(WZ - 1));

        float img;
        if (inwin) {
            // zero OOB weights -> exact zeros padding (values may be clamped)
            float wx0 = ((unsigned)x0       < (unsigned)WW) ? (1.0f - txf) : 0.0f;
            float wx1 = ((unsigned)(x0 + 1) < (unsigned)WW) ? txf : 0.0f;
            float wy0 = ((unsigned)y0       < (unsigned)HH) ? (1.0f - tyf) : 0.0f;
            float wy1 = ((unsigned)(y0 + 1) < (unsigned)HH) ? tyf : 0.0f;
            float wz0 = ((unsigned)z0       < (unsigned)DD) ? (1.0f - tzf) : 0.0f;
            float wz1 = ((unsigned)(z0 + 1) < (unsigned)DD) ? tzf : 0.0f;

            int b00 = (zi * WY + yi) * WX + xi;
            int b01 = b00 + WX;
            int b10 = b00 + WY * WX;
            int b11 = b10 + WX;

            float r00 = fmaf(tile[b00], wx0, tile[b00 + 1] * wx1);
            float r01 = fmaf(tile[b01], wx0, tile[b01 + 1] * wx1);
            float r10 = fmaf(tile[b10], wx0, tile[b10 + 1] * wx1);
            float r11 = fmaf(tile[b11], wx0, tile[b11 + 1] * wx1);

            img = wz0 * fmaf(wy0, r00, wy1 * r01)
                + wz1 * fmaf(wy0, r10, wy1 * r11);
        } else {
            img = sample1_global(src, sx, sy, sz);
        }

        out[idx]          = img;
        out[DHW + idx]    = oz;
        out[2u*DHW + idx] = oy;
        out[3u*DHW + idx] = ox;
    }
}

extern "C" void kernel_launch(void* const* d_in, const int* in_sizes, int n_in,
                              void* d_out, int out_size) {
    const float* src   = (const float*)d_in[0];
    const float* flow1 = (const float*)d_in[1];
    const float* flow2 = (const float*)d_in[2];
    // d_in[3] meshgrid — analytic, not loaded
    const float* rf    = (const float*)d_in[4];
    float* out = (float*)d_out;

    dim3 block(32, 8);
    dim3 grid(WW / TX, HH / TY, DD / TZ);
    st_kernel<<<grid, block>>>(src, flow1, flow2, rf, out);
}

// round 11
// speedup vs baseline: 2.8098x; 1.9834x over previous
#include <cuda_runtime.h>

#define DD 160
#define HH 192
#define WW 160
#define DHW (DD*HH*WW)

// Branchless trilinear prep: clamped offsets + masked weights.
// OOB corners get zero weight (exact zeros padding); loads stay in-bounds.
struct Prep {
    int   off0[4];   // row base + x0c for the 4 (z,y) corner rows
    int   dx1;       // x1c - x0c (0 at border, else 1)
    float wr[4];     // (z,y) corner weights with bounds masks
    float wx0, wx1;  // x corner weights with bounds masks
};

__device__ __forceinline__ void prep_sample(float ix, float iy, float iz, Prep& p) {
    float x0f = floorf(ix), y0f = floorf(iy), z0f = floorf(iz);
    int x0 = (int)x0f, y0 = (int)y0f, z0 = (int)z0f;
    float tx = ix - x0f, ty = iy - y0f, tz = iz - z0f;

    int x0c = min(max(x0, 0), WW - 1);
    int x1c = min(max(x0 + 1, 0), WW - 1);
    p.dx1 = x1c - x0c;
    p.wx0 = ((unsigned)x0       < (unsigned)WW) ? (1.0f - tx) : 0.0f;
    p.wx1 = ((unsigned)(x0 + 1) < (unsigned)WW) ? tx : 0.0f;

    float wy0 = ((unsigned)y0       < (unsigned)HH) ? (1.0f - ty) : 0.0f;
    float wy1 = ((unsigned)(y0 + 1) < (unsigned)HH) ? ty : 0.0f;
    float wz0 = ((unsigned)z0       < (unsigned)DD) ? (1.0f - tz) : 0.0f;
    float wz1 = ((unsigned)(z0 + 1) < (unsigned)DD) ? tz : 0.0f;

    int y0c = min(max(y0, 0), HH - 1);
    int y1c = min(max(y0 + 1, 0), HH - 1);
    int z0c = min(max(z0, 0), DD - 1);
    int z1c = min(max(z0 + 1, 0), DD - 1);

    int b00 = (z0c * HH + y0c) * WW + x0c;
    int b01 = (z0c * HH + y1c) * WW + x0c;
    int b10 = (z1c * HH + y0c) * WW + x0c;
    int b11 = (z1c * HH + y1c) * WW + x0c;
    p.off0[0] = b00; p.off0[1] = b01; p.off0[2] = b10; p.off0[3] = b11;
    p.wr[0] = wz0 * wy0; p.wr[1] = wz0 * wy1;
    p.wr[2] = wz1 * wy0; p.wr[3] = wz1 * wy1;
}

__device__ __forceinline__ void sample3(const float* __restrict__ v,
                                        float ix, float iy, float iz,
                                        float& o0, float& o1, float& o2) {
    o0 = 0.0f; o1 = 0.0f; o2 = 0.0f;
    // practically always fully out of bounds -> warp-uniform early-out
    if (ix <= -1.0f || ix >= (float)WW ||
        iy <= -1.0f || iy >= (float)HH ||
        iz <= -1.0f || iz >= (float)DD) return;
    float x0f = floorf(ix), y0f = floorf(iy), z0f = floorf(iz);
    int x0 = (int)x0f, y0 = (int)y0f, z0 = (int)z0f;
    float tx = ix - x0f, ty = iy - y0f, tz = iz - z0f;
    #pragma unroll
    for (int dz = 0; dz < 2; dz++) {
        int zc = z0 + dz;
        if ((unsigned)zc >= (unsigned)DD) continue;
        float wz = dz ? tz : 1.0f - tz;
        #pragma unroll
        for (int dy = 0; dy < 2; dy++) {
            int yc = y0 + dy;
            if ((unsigned)yc >= (unsigned)HH) continue;
            float wy = dy ? ty : 1.0f - ty;
            float wzy = wz * wy;
            unsigned base = ((unsigned)zc * HH + (unsigned)yc) * WW;
            #pragma unroll
            for (int dx = 0; dx < 2; dx++) {
                int xc = x0 + dx;
                if ((unsigned)xc >= (unsigned)WW) continue;
                float w = wzy * (dx ? tx : 1.0f - tx);
                unsigned off = base + (unsigned)xc;
                o0 = fmaf(w, __ldg(v + off), o0);
                o1 = fmaf(w, __ldg(v + DHW + off), o1);
                o2 = fmaf(w, __ldg(v + 2u*DHW + off), o2);
            }
        }
    }
}

// Compute phase for one voxel: coords -> out_flow -> src sample coords -> Prep
__device__ __forceinline__ void compute_voxel(
        const float* __restrict__ flow1, float rf,
        float xf, float yf, float zf,
        float f2z, float f2y, float f2x,
        float& oz, float& oy, float& ox, Prep& p) {
    // grid2 = grid + flow2 * rf  (grid analytic)
    float g2z = zf + f2z * rf;
    float g2y = yf + f2y * rf;
    float g2x = xf + f2x * rf;

    // grid_sample(flow1, grid2) unnorm (align_corners=False)
    float ix1 = ((g2x + 1.0f) * (float)WW - 1.0f) * 0.5f;
    float iy1 = ((g2y + 1.0f) * (float)HH - 1.0f) * 0.5f;
    float iz1 = ((g2z + 1.0f) * (float)DD - 1.0f) * 0.5f;

    float w0, w1, w2;
    sample3(flow1, ix1, iy1, iz1, w0, w1, w2);

    oz = w0 + f2z;
    oy = w1 + f2y;
    ox = w2 + f2x;

    float vz = zf + oz * rf;
    float vy = yf + oy * rf;
    float vx = xf + ox * rf;

    float nz = 2.0f * (vz / (float)(DD - 1) - 0.5f);
    float ny = 2.0f * (vy / (float)(HH - 1) - 0.5f);
    float nx = 2.0f * (vx / (float)(WW - 1) - 0.5f);

    float sx = ((nx + 1.0f) * (float)WW - 1.0f) * 0.5f;
    float sy = ((ny + 1.0f) * (float)HH - 1.0f) * 0.5f;
    float sz = ((nz + 1.0f) * (float)DD - 1.0f) * 0.5f;

    prep_sample(sx, sy, sz, p);
}

// block (32,4): warp = 32 stride-1 x at one (y,z); thread handles 4 consecutive y
__global__ void __launch_bounds__(128) st_kernel(
                          const float* __restrict__ src,
                          const float* __restrict__ flow1,
                          const float* __restrict__ flow2,
                          const float* __restrict__ rf_p,
                          float* __restrict__ out) {
    unsigned x  = blockIdx.x * 32u + threadIdx.x;
    unsigned z  = blockIdx.z;
    unsigned yb = blockIdx.y * 16u + threadIdx.y * 4u;

    float rf = __ldg(rf_p);
    float xf = (float)x, zf = (float)z;

    unsigned idx0 = (z * HH + yb) * WW + x;

    // front-batched flow2 loads (MLP = 12)
    float f2z[4], f2y[4], f2x[4];
    #pragma unroll
    for (int j = 0; j < 4; j++) {
        unsigned idx = idx0 + j * WW;
        f2z[j] = __ldg(flow2 + idx);
        f2y[j] = __ldg(flow2 + DHW + idx);
        f2x[j] = __ldg(flow2 + 2u*DHW + idx);
    }

    // process j in pairs: 16 gather loads in flight per pair
    #pragma unroll
    for (int jp = 0; jp < 2; jp++) {
        int j0 = jp * 2, j1 = jp * 2 + 1;
        float oz0, oy0, ox0, oz1, oy1, ox1;
        Prep p0, p1;
        compute_voxel(flow1, rf, xf, (float)(yb + j0), zf,
                      f2z[j0], f2y[j0], f2x[j0], oz0, oy0, ox0, p0);
        compute_voxel(flow1, rf, xf, (float)(yb + j1), zf,
                      f2z[j1], f2y[j1], f2x[j1], oz1, oy1, ox1, p1);

        // 16 independent gathers, issued back-to-back
        float a0[4], b0[4], a1[4], b1[4];
        #pragma unroll
        for (int r = 0; r < 4; r++) {
            a0[r] = __ldg(src + p0.off0[r]);
            b0[r] = __ldg(src + p0.off0[r] + p0.dx1);
            a1[r] = __ldg(src + p1.off0[r]);
            b1[r] = __ldg(src + p1.off0[r] + p1.dx1);
        }

        float img0 = 0.0f, img1 = 0.0f;
        #pragma unroll
        for (int r = 0; r < 4; r++) {
            img0 = fmaf(p0.wr[r], fmaf(a0[r], p0.wx0, b0[r] * p0.wx1), img0);
            img1 = fmaf(p1.wr[r], fmaf(a1[r], p1.wx0, b1[r] * p1.wx1), img1);
        }

        unsigned idxA = idx0 + j0 * WW;
        unsigned idxB = idx0 + j1 * WW;
        out[idxA]          = img0;
        out[DHW + idxA]    = oz0;
        out[2u*DHW + idxA] = oy0;
        out[3u*DHW + idxA] = ox0;
        out[idxB]          = img1;
        out[DHW + idxB]    = oz1;
        out[2u*DHW + idxB] = oy1;
        out[3u*DHW + idxB] = ox1;
    }
}

extern "C" void kernel_launch(void* const* d_in, const int* in_sizes, int n_in,
                              void* d_out, int out_size) {
    const float* src   = (const float*)d_in[0];
    const float* flow1 = (const float*)d_in[1];
    const float* flow2 = (const float*)d_in[2];
    // d_in[3] meshgrid — analytic, not loaded
    const float* rf    = (const float*)d_in[4];
    float* out = (float*)d_out;

    dim3 block(32, 4);
    dim3 grid(WW / 32, HH / 16, DD);
    st_kernel<<<grid, block>>>(src, flow1, flow2, rf, out);
}

// round 12
// speedup vs baseline: 2.9003x; 1.0322x over previous
#include <cuda_runtime.h>

#define DD 160
#define HH 192
#define WW 160
#define DHW (DD*HH*WW)

// Exact algebraic collapse of reference coordinate chain:
//   sample coord = v * (S/(S-1)) - 0.5,  v = grid + out_flow*rf
#define CSX (160.0f/159.0f)
#define CSY (192.0f/191.0f)
#define CSZ (160.0f/159.0f)
// First sampler unnorm: ix = ((g+1)*S - 1)/2 = g*(S/2) + (S-1)/2
#define UAX 80.0f
#define UBX 79.5f
#define UAY 96.0f
#define UBY 95.5f
#define UAZ 80.0f
#define UBZ 79.5f

// Branchless trilinear prep: clamped offsets + masked weights.
struct Prep {
    int   off[4];    // 4 (z,y) corner rows + x0c
    int   dx1;       // x1c - x0c (0 at border, else 1)
    float wr[4];     // (z,y) corner weights, bounds-masked
    float wx0, wx1;  // x weights, bounds-masked
};

__device__ __forceinline__ void prep_sample(float ix, float iy, float iz, Prep& p) {
    float x0f = floorf(ix), y0f = floorf(iy), z0f = floorf(iz);
    int x0 = (int)x0f, y0 = (int)y0f, z0 = (int)z0f;
    float tx = ix - x0f, ty = iy - y0f, tz = iz - z0f;

    int x0c = min(max(x0, 0), WW - 1);
    int x1c = min(max(x0 + 1, 0), WW - 1);
    p.dx1 = x1c - x0c;
    p.wx0 = ((unsigned)x0       < (unsigned)WW) ? (1.0f - tx) : 0.0f;
    p.wx1 = ((unsigned)(x0 + 1) < (unsigned)WW) ? tx : 0.0f;

    float wy0 = ((unsigned)y0       < (unsigned)HH) ? (1.0f - ty) : 0.0f;
    float wy1 = ((unsigned)(y0 + 1) < (unsigned)HH) ? ty : 0.0f;
    float wz0 = ((unsigned)z0       < (unsigned)DD) ? (1.0f - tz) : 0.0f;
    float wz1 = ((unsigned)(z0 + 1) < (unsigned)DD) ? tz : 0.0f;

    int y0c = min(max(y0, 0), HH - 1);
    int y1c = min(max(y0 + 1, 0), HH - 1);
    int z0c = min(max(z0, 0), DD - 1);
    int z1c = min(max(z0 + 1, 0), DD - 1);

    int rz0 = z0c * (HH * WW) + x0c;
    int rz1 = z1c * (HH * WW) + x0c;
    p.off[0] = rz0 + y0c * WW;
    p.off[1] = rz0 + y1c * WW;
    p.off[2] = rz1 + y0c * WW;
    p.off[3] = rz1 + y1c * WW;
    p.wr[0] = wz0 * wy0; p.wr[1] = wz0 * wy1;
    p.wr[2] = wz1 * wy0; p.wr[3] = wz1 * wy1;
}

__device__ __forceinline__ void sample3(const float* __restrict__ v,
                                        float ix, float iy, float iz,
                                        float& o0, float& o1, float& o2) {
    o0 = 0.0f; o1 = 0.0f; o2 = 0.0f;
    // practically always fully out of bounds -> warp-uniform early-out
    if (ix <= -1.0f || ix >= (float)WW ||
        iy <= -1.0f || iy >= (float)HH ||
        iz <= -1.0f || iz >= (float)DD) return;
    float x0f = floorf(ix), y0f = floorf(iy), z0f = floorf(iz);
    int x0 = (int)x0f, y0 = (int)y0f, z0 = (int)z0f;
    float tx = ix - x0f, ty = iy - y0f, tz = iz - z0f;
    #pragma unroll
    for (int dz = 0; dz < 2; dz++) {
        int zc = z0 + dz;
        if ((unsigned)zc >= (unsigned)DD) continue;
        float wz = dz ? tz : 1.0f - tz;
        #pragma unroll
        for (int dy = 0; dy < 2; dy++) {
            int yc = y0 + dy;
            if ((unsigned)yc >= (unsigned)HH) continue;
            float wy = dy ? ty : 1.0f - ty;
            float wzy = wz * wy;
            unsigned base = ((unsigned)zc * HH + (unsigned)yc) * WW;
            #pragma unroll
            for (int dx = 0; dx < 2; dx++) {
                int xc = x0 + dx;
                if ((unsigned)xc >= (unsigned)WW) continue;
                float w = wzy * (dx ? tx : 1.0f - tx);
                unsigned off = base + (unsigned)xc;
                o0 = fmaf(w, __ldg(v + off), o0);
                o1 = fmaf(w, __ldg(v + DHW + off), o1);
                o2 = fmaf(w, __ldg(v + 2u*DHW + off), o2);
            }
        }
    }
}

__device__ __forceinline__ void compute_voxel(
        const float* __restrict__ flow1, float rf,
        float xf, float yf, float zf,
        float f2z, float f2y, float f2x,
        float& oz, float& oy, float& ox, Prep& p) {
    // grid2 = grid + flow2 * rf
    float g2z = fmaf(f2z, rf, zf);
    float g2y = fmaf(f2y, rf, yf);
    float g2x = fmaf(f2x, rf, xf);

    // first sampler unnorm (collapsed)
    float ix1 = fmaf(g2x, UAX, UBX);
    float iy1 = fmaf(g2y, UAY, UBY);
    float iz1 = fmaf(g2z, UAZ, UBZ);

    float w0, w1, w2;
    sample3(flow1, ix1, iy1, iz1, w0, w1, w2);

    oz = w0 + f2z;
    oy = w1 + f2y;
    ox = w2 + f2x;

    // second sampler coords (collapsed): s = v*(S/(S-1)) - 0.5
    float vz = fmaf(oz, rf, zf);
    float vy = fmaf(oy, rf, yf);
    float vx = fmaf(ox, rf, xf);

    float sx = fmaf(vx, CSX, -0.5f);
    float sy = fmaf(vy, CSY, -0.5f);
    float sz = fmaf(vz, CSZ, -0.5f);

    prep_sample(sx, sy, sz, p);
}

// block (32,8): warp = 32 stride-1 x at one (y,z); thread handles 4 consecutive y
__global__ void __launch_bounds__(256) st_kernel(
                          const float* __restrict__ src,
                          const float* __restrict__ flow1,
                          const float* __restrict__ flow2,
                          const float* __restrict__ rf_p,
                          float* __restrict__ out) {
    unsigned x  = blockIdx.x * 32u + threadIdx.x;
    unsigned z  = blockIdx.z;
    unsigned yb = blockIdx.y * 32u + threadIdx.y * 4u;

    float rf = __ldg(rf_p);
    float xf = (float)x, zf = (float)z;

    unsigned idx0 = (z * HH + yb) * WW + x;

    // front-batched flow2 loads (MLP = 12)
    float f2z[4], f2y[4], f2x[4];
    #pragma unroll
    for (int j = 0; j < 4; j++) {
        unsigned idx = idx0 + j * WW;
        f2z[j] = __ldg(flow2 + idx);
        f2y[j] = __ldg(flow2 + DHW + idx);
        f2x[j] = __ldg(flow2 + 2u*DHW + idx);
    }

    // process j in pairs: 16 gather loads in flight per pair
    #pragma unroll
    for (int jp = 0; jp < 2; jp++) {
        int j0 = jp * 2, j1 = jp * 2 + 1;
        float oz0, oy0, ox0, oz1, oy1, ox1;
        Prep p0, p1;
        compute_voxel(flow1, rf, xf, (float)(yb + j0), zf,
                      f2z[j0], f2y[j0], f2x[j0], oz0, oy0, ox0, p0);
        compute_voxel(flow1, rf, xf, (float)(yb + j1), zf,
                      f2z[j1], f2y[j1], f2x[j1], oz1, oy1, ox1, p1);

        // 16 independent gathers issued back-to-back
        float a0[4], b0[4], a1[4], b1[4];
        #pragma unroll
        for (int r = 0; r < 4; r++) {
            a0[r] = __ldg(src + p0.off[r]);
            b0[r] = __ldg(src + p0.off[r] + p0.dx1);
            a1[r] = __ldg(src + p1.off[r]);
            b1[r] = __ldg(src + p1.off[r] + p1.dx1);
        }

        float img0 = 0.0f, img1 = 0.0f;
        #pragma unroll
        for (int r = 0; r < 4; r++) {
            img0 = fmaf(p0.wr[r], fmaf(a0[r], p0.wx0, b0[r] * p0.wx1), img0);
            img1 = fmaf(p1.wr[r], fmaf(a1[r], p1.wx0, b1[r] * p1.wx1), img1);
        }

        // streaming stores: keep L2 for src gathers
        unsigned idxA = idx0 + j0 * WW;
        unsigned idxB = idx0 + j1 * WW;
        __stcs(out + idxA,            img0);
        __stcs(out + DHW + idxA,      oz0);
        __stcs(out + 2u*DHW + idxA,   oy0);
        __stcs(out + 3u*DHW + idxA,   ox0);
        __stcs(out + idxB,            img1);
        __stcs(out + DHW + idxB,      oz1);
        __stcs(out + 2u*DHW + idxB,   oy1);
        __stcs(out + 3u*DHW + idxB,   ox1);
    }
}

extern "C" void kernel_launch(void* const* d_in, const int* in_sizes, int n_in,
                              void* d_out, int out_size) {
    const float* src   = (const float*)d_in[0];
    const float* flow1 = (const float*)d_in[1];
    const float* flow2 = (const float*)d_in[2];
    // d_in[3] meshgrid — analytic, not loaded
    const float* rf    = (const float*)d_in[4];
    float* out = (float*)d_out;

    dim3 block(32, 8);
    dim3 grid(WW / 32, HH / 32, DD);
    st_kernel<<<grid, block>>>(src, flow1, flow2, rf, out);
}